// round 16
// baseline (speedup 1.0000x reference)
#include <cuda_runtime.h>
#include <cuda_bf16.h>
#include <math.h>
#include <cstdint>

#define NV   100000
#define NE   10000
#define NP   1600000
#define CIN  256
#define CMID 128
#define COUT 64
#define NEG  0.2f

// ---------------- scratch (device globals; no allocation allowed) ----------
__device__ float g_h[NV * COUT];        // MLP output h (f32, exact path)
__device__ __nv_bfloat16 g_hb[NV * COUT];   // bf16 shadow of h (scatter reads)
__device__ __nv_bfloat16 g_efb[NE * COUT];  // bf16 e_feat (scatter reads)
__device__ float g_esum[NE * COUT];     // hyperedge accumulator
__device__ float g_ecnt[NE];            // hyperedge degree
__device__ float g_hgsum[NV * COUT];    // e2v accumulator
__device__ float g_gsum[NV * COUT];     // graph accumulator
__device__ float g_vcnt_hg[NV];         // vertex incidence degree
__device__ float g_vcnt_g[NV];          // vertex graph in-degree

__device__ __forceinline__ float lrelu(float v) { return v > 0.f ? v : NEG * v; }

__device__ __forceinline__ uint32_t cvt_tf32(float f) {
    uint32_t u;
    asm("cvt.rna.tf32.f32 %0, %1;" : "=r"(u) : "f"(f));
    return u;
}
__device__ __forceinline__ void mma_tf32(float* c, const uint32_t* a,
                                         const uint32_t* b) {
    asm volatile(
        "mma.sync.aligned.m16n8k8.row.col.f32.tf32.tf32.f32 "
        "{%0,%1,%2,%3}, {%4,%5,%6,%7}, {%8,%9}, {%0,%1,%2,%3};"
        : "+f"(c[0]), "+f"(c[1]), "+f"(c[2]), "+f"(c[3])
        : "r"(a[0]), "r"(a[1]), "r"(a[2]), "r"(a[3]), "r"(b[0]), "r"(b[1]));
}
__device__ __forceinline__ void red_add1(float* p) {
    asm volatile("red.global.add.f32 [%0], %1;" :: "l"(p), "f"(1.0f) : "memory");
}

// ---------------- zero count arrays (tiny prelaunch) ------------------------
__global__ void zero_cnt_kernel() {
    int i = blockIdx.x * blockDim.x + threadIdx.x;
    if (i < NE) g_ecnt[i] = 0.f;
    if (i < NV) { g_vcnt_hg[i] = 0.f; g_vcnt_g[i] = 0.f; }
}

// ========== fused MLP (mma.sync tf32): h = lrelu(x@W1+b1)@W2 + b2 ==========
// Persistent 148 CTAs, 256 threads. GM=192 rows/tile, fragment-paired
// weights, double-buffered register-prefetch A staging. Head also zeroes the
// big accumulators AND computes all three degree histograms (fire-and-forget
// REDs absorbed by the idle LSU during compute).
#define GM     192
#define PW1R   264          // W1p row stride (words)
#define PW2R   136          // W2p row stride (words)
#define PA     36           // A-chunk row stride (words), bank 4g+t clean
#define SM_W1  0
#define SM_W2  (128 * PW1R)                  // 33792
#define SM_A0  (SM_W2 + 64 * PW2R)           // 42496
#define SM_A1  (SM_A0 + GM * PA)             // 49408
#define SM_B1  (SM_A1 + GM * PA)             // 56320
#define SM_B2  (SM_B1 + CMID)                // 56448
#define GF_WORDS (SM_B2 + COUT)              // 56512 words = 226048 B
#define GF_SMEM_BYTES (GF_WORDS * 4)

__global__ __launch_bounds__(256, 1)
void gemm_fused(const float* __restrict__ x, const float* __restrict__ W1,
                const float* __restrict__ b1, const float* __restrict__ W2,
                const float* __restrict__ b2,
                const int* __restrict__ hg_v, const int* __restrict__ hg_e,
                const int* __restrict__ g_dst) {
    extern __shared__ uint32_t sm[];
    uint32_t* W1p = sm + SM_W1;
    uint32_t* W2p = sm + SM_W2;
    float*    b1s = (float*)(sm + SM_B1);
    float*    b2s = (float*)(sm + SM_B2);

    int tid = threadIdx.x, wid = tid >> 5, lane = tid & 31;
    int g = lane >> 2, t = lane & 3;
    int m0 = (wid & 3) * 48;        // warp row block (3 m16-tiles)
    int n1 = (wid >> 2) * 64;       // GEMM1 col block / mid half
    int n2 = (wid >> 2) * 32;       // GEMM2 col block

    // ---- fused accumulator zeroing + degree histograms (grid-stride) ----
    {
        int gstride = gridDim.x * blockDim.x;
        int gt = blockIdx.x * blockDim.x + tid;
        float4 z = make_float4(0.f, 0.f, 0.f, 0.f);
        for (int i = gt; i < NV * COUT / 4; i += gstride) {
            ((float4*)g_hgsum)[i] = z;
            ((float4*)g_gsum)[i]  = z;
            if (i < NE * COUT / 4) ((float4*)g_esum)[i] = z;
        }
        for (int i = gt; i < NP; i += gstride) {
            red_add1(&g_ecnt[__ldg(hg_e + i)]);
            red_add1(&g_vcnt_hg[__ldg(hg_v + i)]);
            red_add1(&g_vcnt_g[__ldg(g_dst + i)]);
        }
    }

    // ---- stage weights in fragment-paired layout ----
    for (int i = tid; i < CIN * CMID; i += 256) {
        int k = i >> 7, n = i & 127;
        int row = (k >> 3) * 4 + (k & 3);
        int e = (k >> 2) & 1;
        W1p[row * PW1R + n * 2 + e] = cvt_tf32(W1[i]);
    }
    for (int i = tid; i < CMID * COUT; i += 256) {
        int k = i >> 6, n = i & 63;
        int row = (k >> 3) * 4 + (k & 3);
        int e = (k >> 2) & 1;
        W2p[row * PW2R + n * 2 + e] = cvt_tf32(W2[i]);
    }
    if (tid < CMID) b1s[tid] = b1[tid];
    if (tid < COUT) b2s[tid] = b2[tid];

    int ntiles = (NV + GM - 1) / GM;   // 521
    for (int tile = blockIdx.x; tile < ntiles; tile += gridDim.x) {
        int row0 = tile * GM;

        float c1[3][8][4];
#pragma unroll
        for (int mt = 0; mt < 3; mt++)
#pragma unroll
            for (int nt = 0; nt < 8; nt++)
#pragma unroll
                for (int q = 0; q < 4; q++) c1[mt][nt][q] = 0.f;

        float4 pre[6];
#pragma unroll
        for (int p = 0; p < 6; p++) {
            int i = tid * 4 + p * 1024;
            int r = i >> 5, kk = i & 31;
            int grow = row0 + r;
            pre[p] = (grow < NV)
                ? *(const float4*)(x + (size_t)grow * CIN + kk)
                : make_float4(0.f, 0.f, 0.f, 0.f);
        }
        __syncthreads();   // buffers free from previous tile

        for (int kc = 0; kc < 8; kc++) {
            uint32_t* buf = sm + ((kc & 1) ? SM_A1 : SM_A0);
#pragma unroll
            for (int p = 0; p < 6; p++) {
                int i = tid * 4 + p * 1024;
                int r = i >> 5, kk = i & 31;
                uint4 tv;
                tv.x = cvt_tf32(pre[p].x); tv.y = cvt_tf32(pre[p].y);
                tv.z = cvt_tf32(pre[p].z); tv.w = cvt_tf32(pre[p].w);
                *(uint4*)(buf + r * PA + kk) = tv;
            }
            if (kc < 7) {
#pragma unroll
                for (int p = 0; p < 6; p++) {
                    int i = tid * 4 + p * 1024;
                    int r = i >> 5, kk = i & 31;
                    int grow = row0 + r;
                    pre[p] = (grow < NV)
                        ? *(const float4*)(x + (size_t)grow * CIN + (kc + 1) * 32 + kk)
                        : make_float4(0.f, 0.f, 0.f, 0.f);
                }
            }
            __syncthreads();   // chunk kc visible to all

#pragma unroll
            for (int s = 0; s < 4; s++) {
                int k0 = s * 8;
                int wrow = ((kc * 4 + s) * 4 + t) * PW1R;
                uint32_t a[3][4];
#pragma unroll
                for (int mt = 0; mt < 3; mt++) {
                    int r = m0 + mt * 16 + g;
                    a[mt][0] = buf[r * PA + k0 + t];
                    a[mt][1] = buf[(r + 8) * PA + k0 + t];
                    a[mt][2] = buf[r * PA + k0 + t + 4];
                    a[mt][3] = buf[(r + 8) * PA + k0 + t + 4];
                }
                uint32_t b[8][2];
#pragma unroll
                for (int nt = 0; nt < 8; nt++) {
                    int n = n1 + nt * 8 + g;
                    uint2 bv = *(const uint2*)(W1p + wrow + n * 2);
                    b[nt][0] = bv.x; b[nt][1] = bv.y;
                }
#pragma unroll
                for (int mt = 0; mt < 3; mt++)
#pragma unroll
                    for (int nt = 0; nt < 8; nt++)
                        mma_tf32(c1[mt][nt], a[mt], b[nt]);
            }
        }

        // ---------------- GEMM2: 4 quarter relays through the buffers ------
        float c2[3][4][4];
#pragma unroll
        for (int mt = 0; mt < 3; mt++)
#pragma unroll
            for (int nt = 0; nt < 4; nt++)
#pragma unroll
                for (int q = 0; q < 4; q++) c2[mt][nt][q] = 0.f;

#pragma unroll
        for (int q = 0; q < 4; q++) {
            uint32_t* buf = sm + ((q & 1) ? SM_A1 : SM_A0);
            if ((wid >> 2) == (q >> 1)) {
                int nt0 = (q & 1) * 4;
#pragma unroll
                for (int mt = 0; mt < 3; mt++) {
                    int r = m0 + mt * 16 + g;
#pragma unroll
                    for (int nt = nt0; nt < nt0 + 4; nt++) {
                        int colg = nt * 8 + 2 * t;          // 0..63 within half
                        int lc   = colg - (q & 1) * 32;     // 0..31 in quarter
                        float bx = b1s[n1 + colg], by = b1s[n1 + colg + 1];
                        uint2 v0, v1;
                        v0.x = cvt_tf32(lrelu(c1[mt][nt][0] + bx));
                        v0.y = cvt_tf32(lrelu(c1[mt][nt][1] + by));
                        v1.x = cvt_tf32(lrelu(c1[mt][nt][2] + bx));
                        v1.y = cvt_tf32(lrelu(c1[mt][nt][3] + by));
                        *(uint2*)(buf + r * PA + lc) = v0;
                        *(uint2*)(buf + (r + 8) * PA + lc) = v1;
                    }
                }
            }
            __syncthreads();
#pragma unroll
            for (int s = 0; s < 4; s++) {
                int k0 = s * 8;
                int wrow = ((q * 4 + s) * 4 + t) * PW2R;
                uint32_t a[3][4];
#pragma unroll
                for (int mt = 0; mt < 3; mt++) {
                    int r = m0 + mt * 16 + g;
                    a[mt][0] = buf[r * PA + k0 + t];
                    a[mt][1] = buf[(r + 8) * PA + k0 + t];
                    a[mt][2] = buf[r * PA + k0 + t + 4];
                    a[mt][3] = buf[(r + 8) * PA + k0 + t + 4];
                }
                uint32_t b[4][2];
#pragma unroll
                for (int nt = 0; nt < 4; nt++) {
                    int n = n2 + nt * 8 + g;
                    uint2 bv = *(const uint2*)(W2p + wrow + n * 2);
                    b[nt][0] = bv.x; b[nt][1] = bv.y;
                }
#pragma unroll
                for (int mt = 0; mt < 3; mt++)
#pragma unroll
                    for (int nt = 0; nt < 4; nt++)
                        mma_tf32(c2[mt][nt], a[mt], b[nt]);
            }
        }

        // ---------------- epilogue: h -> g_h (f32) + g_hb (bf16) -----------
#pragma unroll
        for (int mt = 0; mt < 3; mt++) {
            int r0 = row0 + m0 + mt * 16 + g;
#pragma unroll
            for (int nt = 0; nt < 4; nt++) {
                int col = n2 + nt * 8 + 2 * t;
                float bx = b2s[col], by = b2s[col + 1];
                if (r0 < NV) {
                    float2 o; o.x = c2[mt][nt][0] + bx; o.y = c2[mt][nt][1] + by;
                    *(float2*)(g_h + (size_t)r0 * COUT + col) = o;
                    *(__nv_bfloat162*)(g_hb + (size_t)r0 * COUT + col) =
                        __floats2bfloat162_rn(o.x, o.y);
                }
                if (r0 + 8 < NV) {
                    float2 o; o.x = c2[mt][nt][2] + bx; o.y = c2[mt][nt][3] + by;
                    *(float2*)(g_h + (size_t)(r0 + 8) * COUT + col) = o;
                    *(__nv_bfloat162*)(g_hb + (size_t)(r0 + 8) * COUT + col) =
                        __floats2bfloat162_rn(o.x, o.y);
                }
            }
        }
    }
}

// ---------------- bf16-read scatter helper (no counts) ----------------------
__device__ __forceinline__ void scat_bf16(const __nv_bfloat16* __restrict__ feat,
                                          int s, int d, int l,
                                          float* __restrict__ sum) {
    uint2 raw = *(const uint2*)(feat + (size_t)s * COUT + l * 4);
    float2 lo = __bfloat1622float2(*(__nv_bfloat162*)&raw.x);
    float2 hi = __bfloat1622float2(*(__nv_bfloat162*)&raw.y);
    float* dst = sum + (size_t)d * COUT + l * 4;
    asm volatile("red.global.add.v4.f32 [%0], {%1,%2,%3,%4};"
                 :: "l"(dst), "f"(lo.x), "f"(lo.y), "f"(hi.x), "f"(hi.y)
                 : "memory");
}

// ---------------- merged scatter: v2e + graph (2D grid, y = pass) ----------
__global__ void scatter2_kernel(const int* __restrict__ hg_v,
                                const int* __restrict__ hg_e,
                                const int* __restrict__ g_srcp,
                                const int* __restrict__ g_dstp,
                                float* __restrict__ esum,
                                float* __restrict__ gsum) {
    int t = blockIdx.x * blockDim.x + threadIdx.x;
    int i = t >> 4;
    if (i >= NP) return;
    int l = t & 15;
    if (blockIdx.y == 0)
        scat_bf16(g_hb, __ldg(hg_v + i), __ldg(hg_e + i), l, esum);
    else
        scat_bf16(g_hb, __ldg(g_srcp + i), __ldg(g_dstp + i), l, gsum);
}

// ---------------- e2v scatter (reads bf16 efeat) ----------------------------
__global__ void scatter_e2v_kernel(const int* __restrict__ hg_e,
                                   const int* __restrict__ hg_v,
                                   float* __restrict__ sum) {
    int t = blockIdx.x * blockDim.x + threadIdx.x;
    int i = t >> 4;
    if (i >= NP) return;
    int l = t & 15;
    scat_bf16(g_efb, __ldg(hg_e + i), __ldg(hg_v + i), l, sum);
}

// ---------------- e_feat(bf16) = e_sum / max(cnt,1) -------------------------
__global__ void efeat_kernel() {
    int i = blockIdx.x * blockDim.x + threadIdx.x;   // bf16x2 elements
    if (i >= NE * COUT / 2) return;
    float c = fmaxf(g_ecnt[i >> 5], 1.0f);
    float inv = 1.0f / c;
    float2 v = ((const float2*)g_esum)[i];
    ((__nv_bfloat162*)g_efb)[i] = __floats2bfloat162_rn(v.x * inv, v.y * inv);
}

// ---------------- final fuse + activation ----------------------------------
__global__ void final_kernel(const float* __restrict__ w, float* __restrict__ out) {
    int t = blockIdx.x * blockDim.x + threadIdx.x;
    if (t >= NV * COUT / 4) return;
    int v = t >> 4;
    float e0 = expf(w[0]), e1 = expf(w[1]);
    float sw0 = e0 / (e0 + e1), sw1 = e1 / (e0 + e1);
    float ih = 1.0f / fmaxf(g_vcnt_hg[v], 1.0f);
    float ig = 1.0f / fmaxf(g_vcnt_g[v], 1.0f);
    float4 hg = ((const float4*)g_hgsum)[t];
    float4 gg = ((const float4*)g_gsum)[t];
    float4 h  = ((const float4*)g_h)[t];
    float4 o;
    o.x = lrelu(sw0 * 0.5f * (gg.x * ig + hg.x * ih) + sw1 * h.x);
    o.y = lrelu(sw0 * 0.5f * (gg.y * ig + hg.y * ih) + sw1 * h.y);
    o.z = lrelu(sw0 * 0.5f * (gg.z * ig + hg.z * ih) + sw1 * h.z);
    o.w = lrelu(sw0 * 0.5f * (gg.w * ig + hg.w * ih) + sw1 * h.w);
    ((float4*)out)[t] = o;
}

// ---------------- launch ----------------------------------------------------
extern "C" void kernel_launch(void* const* d_in, const int* in_sizes, int n_in,
                              void* d_out, int out_size) {
    const float* x    = (const float*)d_in[0];
    const float* W1   = (const float*)d_in[1];
    const float* b1   = (const float*)d_in[2];
    const float* W2   = (const float*)d_in[3];
    const float* b2   = (const float*)d_in[4];
    const float* w    = (const float*)d_in[5];
    const int*   hg_v = (const int*)d_in[6];
    const int*   hg_e = (const int*)d_in[7];
    const int*   g_src= (const int*)d_in[8];
    const int*   g_dst= (const int*)d_in[9];
    float* out = (float*)d_out;

    float *p_esum, *p_hgsum, *p_gsum;
    cudaGetSymbolAddress((void**)&p_esum,  g_esum);
    cudaGetSymbolAddress((void**)&p_hgsum, g_hgsum);
    cudaGetSymbolAddress((void**)&p_gsum,  g_gsum);

    cudaFuncSetAttribute(gemm_fused, cudaFuncAttributeMaxDynamicSharedMemorySize,
                         GF_SMEM_BYTES);

    zero_cnt_kernel<<<(NV + 255) / 256, 256>>>();
    gemm_fused<<<148, 256, GF_SMEM_BYTES>>>(x, W1, b1, W2, b2, hg_v, hg_e, g_dst);

    // v2e + graph scatters in one launch (2D grid: y=0 v2e, y=1 graph)
    dim3 sgrid((NP * 16 + 255) / 256, 2);
    scatter2_kernel<<<sgrid, 256>>>(hg_v, hg_e, g_src, g_dst, p_esum, p_gsum);
    efeat_kernel<<<(NE * COUT / 2 + 255) / 256, 256>>>();
    scatter_e2v_kernel<<<(NP * 16 + 255) / 256, 256>>>(hg_e, hg_v, p_hgsum);
    final_kernel<<<(NV * COUT / 4 + 255) / 256, 256>>>(w, out);
}

// round 17
// speedup vs baseline: 1.4938x; 1.4938x over previous
#include <cuda_runtime.h>
#include <cuda_bf16.h>
#include <math.h>
#include <cstdint>

#define NV   100000
#define NE   10000
#define NP   1600000
#define CIN  256
#define CMID 128
#define COUT 64
#define NEG  0.2f

// ---------------- scratch (device globals; no allocation allowed) ----------
__device__ float g_h[NV * COUT];        // MLP output h (f32, exact path)
__device__ __nv_bfloat16 g_hb[NV * COUT];   // bf16 shadow of h (scatter reads)
__device__ __nv_bfloat16 g_efb[NE * COUT];  // bf16 e_feat (scatter reads)
__device__ __align__(256) float g_esum[NE * COUT];   // TMA-reduce targets
__device__ __align__(256) float g_hgsum[NV * COUT];
__device__ __align__(256) float g_gsum[NV * COUT];
__device__ float g_ecnt[NE];
__device__ float g_vcnt_hg[NV];
__device__ float g_vcnt_g[NV];

__device__ __forceinline__ float lrelu(float v) { return v > 0.f ? v : NEG * v; }

__device__ __forceinline__ uint32_t cvt_tf32(float f) {
    uint32_t u;
    asm("cvt.rna.tf32.f32 %0, %1;" : "=r"(u) : "f"(f));
    return u;
}
__device__ __forceinline__ void mma_tf32(float* c, const uint32_t* a,
                                         const uint32_t* b) {
    asm volatile(
        "mma.sync.aligned.m16n8k8.row.col.f32.tf32.tf32.f32 "
        "{%0,%1,%2,%3}, {%4,%5,%6,%7}, {%8,%9}, {%0,%1,%2,%3};"
        : "+f"(c[0]), "+f"(c[1]), "+f"(c[2]), "+f"(c[3])
        : "r"(a[0]), "r"(a[1]), "r"(a[2]), "r"(a[3]), "r"(b[0]), "r"(b[1]));
}

// ========== fused MLP (mma.sync tf32): h = lrelu(x@W1+b1)@W2 + b2 ==========
// R15 structure: GM=192, fragment-paired weights, double-buffered staging.
// Head zeroes accumulators + counts (NO histograms here — R16 lesson).
#define GM     192
#define PW1R   264
#define PW2R   136
#define PA     36
#define SM_W1  0
#define SM_W2  (128 * PW1R)
#define SM_A0  (SM_W2 + 64 * PW2R)
#define SM_A1  (SM_A0 + GM * PA)
#define SM_B1  (SM_A1 + GM * PA)
#define SM_B2  (SM_B1 + CMID)
#define GF_WORDS (SM_B2 + COUT)
#define GF_SMEM_BYTES (GF_WORDS * 4)

__global__ __launch_bounds__(256, 1)
void gemm_fused(const float* __restrict__ x, const float* __restrict__ W1,
                const float* __restrict__ b1, const float* __restrict__ W2,
                const float* __restrict__ b2) {
    extern __shared__ uint32_t sm[];
    uint32_t* W1p = sm + SM_W1;
    uint32_t* W2p = sm + SM_W2;
    float*    b1s = (float*)(sm + SM_B1);
    float*    b2s = (float*)(sm + SM_B2);

    int tid = threadIdx.x, wid = tid >> 5, lane = tid & 31;
    int g = lane >> 2, t = lane & 3;
    int m0 = (wid & 3) * 48;
    int n1 = (wid >> 2) * 64;
    int n2 = (wid >> 2) * 32;

    {
        int gstride = gridDim.x * blockDim.x;
        int gt = blockIdx.x * blockDim.x + tid;
        float4 z = make_float4(0.f, 0.f, 0.f, 0.f);
        for (int i = gt; i < NV * COUT / 4; i += gstride) {
            ((float4*)g_hgsum)[i] = z;
            ((float4*)g_gsum)[i]  = z;
            if (i < NE * COUT / 4) ((float4*)g_esum)[i] = z;
            if (i < NE)            g_ecnt[i] = 0.f;
            if (i < NV) { g_vcnt_hg[i] = 0.f; g_vcnt_g[i] = 0.f; }
        }
    }

    for (int i = tid; i < CIN * CMID; i += 256) {
        int k = i >> 7, n = i & 127;
        int row = (k >> 3) * 4 + (k & 3);
        int e = (k >> 2) & 1;
        W1p[row * PW1R + n * 2 + e] = cvt_tf32(W1[i]);
    }
    for (int i = tid; i < CMID * COUT; i += 256) {
        int k = i >> 6, n = i & 63;
        int row = (k >> 3) * 4 + (k & 3);
        int e = (k >> 2) & 1;
        W2p[row * PW2R + n * 2 + e] = cvt_tf32(W2[i]);
    }
    if (tid < CMID) b1s[tid] = b1[tid];
    if (tid < COUT) b2s[tid] = b2[tid];

    int ntiles = (NV + GM - 1) / GM;
    for (int tile = blockIdx.x; tile < ntiles; tile += gridDim.x) {
        int row0 = tile * GM;

        float c1[3][8][4];
#pragma unroll
        for (int mt = 0; mt < 3; mt++)
#pragma unroll
            for (int nt = 0; nt < 8; nt++)
#pragma unroll
                for (int q = 0; q < 4; q++) c1[mt][nt][q] = 0.f;

        float4 pre[6];
#pragma unroll
        for (int p = 0; p < 6; p++) {
            int i = tid * 4 + p * 1024;
            int r = i >> 5, kk = i & 31;
            int grow = row0 + r;
            pre[p] = (grow < NV)
                ? *(const float4*)(x + (size_t)grow * CIN + kk)
                : make_float4(0.f, 0.f, 0.f, 0.f);
        }
        __syncthreads();

        for (int kc = 0; kc < 8; kc++) {
            uint32_t* buf = sm + ((kc & 1) ? SM_A1 : SM_A0);
#pragma unroll
            for (int p = 0; p < 6; p++) {
                int i = tid * 4 + p * 1024;
                int r = i >> 5, kk = i & 31;
                uint4 tv;
                tv.x = cvt_tf32(pre[p].x); tv.y = cvt_tf32(pre[p].y);
                tv.z = cvt_tf32(pre[p].z); tv.w = cvt_tf32(pre[p].w);
                *(uint4*)(buf + r * PA + kk) = tv;
            }
            if (kc < 7) {
#pragma unroll
                for (int p = 0; p < 6; p++) {
                    int i = tid * 4 + p * 1024;
                    int r = i >> 5, kk = i & 31;
                    int grow = row0 + r;
                    pre[p] = (grow < NV)
                        ? *(const float4*)(x + (size_t)grow * CIN + (kc + 1) * 32 + kk)
                        : make_float4(0.f, 0.f, 0.f, 0.f);
                }
            }
            __syncthreads();

#pragma unroll
            for (int s = 0; s < 4; s++) {
                int k0 = s * 8;
                int wrow = ((kc * 4 + s) * 4 + t) * PW1R;
                uint32_t a[3][4];
#pragma unroll
                for (int mt = 0; mt < 3; mt++) {
                    int r = m0 + mt * 16 + g;
                    a[mt][0] = buf[r * PA + k0 + t];
                    a[mt][1] = buf[(r + 8) * PA + k0 + t];
                    a[mt][2] = buf[r * PA + k0 + t + 4];
                    a[mt][3] = buf[(r + 8) * PA + k0 + t + 4];
                }
                uint32_t b[8][2];
#pragma unroll
                for (int nt = 0; nt < 8; nt++) {
                    int n = n1 + nt * 8 + g;
                    uint2 bv = *(const uint2*)(W1p + wrow + n * 2);
                    b[nt][0] = bv.x; b[nt][1] = bv.y;
                }
#pragma unroll
                for (int mt = 0; mt < 3; mt++)
#pragma unroll
                    for (int nt = 0; nt < 8; nt++)
                        mma_tf32(c1[mt][nt], a[mt], b[nt]);
            }
        }

        float c2[3][4][4];
#pragma unroll
        for (int mt = 0; mt < 3; mt++)
#pragma unroll
            for (int nt = 0; nt < 4; nt++)
#pragma unroll
                for (int q = 0; q < 4; q++) c2[mt][nt][q] = 0.f;

#pragma unroll
        for (int q = 0; q < 4; q++) {
            uint32_t* buf = sm + ((q & 1) ? SM_A1 : SM_A0);
            if ((wid >> 2) == (q >> 1)) {
                int nt0 = (q & 1) * 4;
#pragma unroll
                for (int mt = 0; mt < 3; mt++) {
                    int r = m0 + mt * 16 + g;
#pragma unroll
                    for (int nt = nt0; nt < nt0 + 4; nt++) {
                        int colg = nt * 8 + 2 * t;
                        int lc   = colg - (q & 1) * 32;
                        float bx = b1s[n1 + colg], by = b1s[n1 + colg + 1];
                        uint2 v0, v1;
                        v0.x = cvt_tf32(lrelu(c1[mt][nt][0] + bx));
                        v0.y = cvt_tf32(lrelu(c1[mt][nt][1] + by));
                        v1.x = cvt_tf32(lrelu(c1[mt][nt][2] + bx));
                        v1.y = cvt_tf32(lrelu(c1[mt][nt][3] + by));
                        *(uint2*)(buf + r * PA + lc) = v0;
                        *(uint2*)(buf + (r + 8) * PA + lc) = v1;
                    }
                }
            }
            __syncthreads();
#pragma unroll
            for (int s = 0; s < 4; s++) {
                int k0 = s * 8;
                int wrow = ((q * 4 + s) * 4 + t) * PW2R;
                uint32_t a[3][4];
#pragma unroll
                for (int mt = 0; mt < 3; mt++) {
                    int r = m0 + mt * 16 + g;
                    a[mt][0] = buf[r * PA + k0 + t];
                    a[mt][1] = buf[(r + 8) * PA + k0 + t];
                    a[mt][2] = buf[r * PA + k0 + t + 4];
                    a[mt][3] = buf[(r + 8) * PA + k0 + t + 4];
                }
                uint32_t b[4][2];
#pragma unroll
                for (int nt = 0; nt < 4; nt++) {
                    int n = n2 + nt * 8 + g;
                    uint2 bv = *(const uint2*)(W2p + wrow + n * 2);
                    b[nt][0] = bv.x; b[nt][1] = bv.y;
                }
#pragma unroll
                for (int mt = 0; mt < 3; mt++)
#pragma unroll
                    for (int nt = 0; nt < 4; nt++)
                        mma_tf32(c2[mt][nt], a[mt], b[nt]);
            }
        }

#pragma unroll
        for (int mt = 0; mt < 3; mt++) {
            int r0 = row0 + m0 + mt * 16 + g;
#pragma unroll
            for (int nt = 0; nt < 4; nt++) {
                int col = n2 + nt * 8 + 2 * t;
                float bx = b2s[col], by = b2s[col + 1];
                if (r0 < NV) {
                    float2 o; o.x = c2[mt][nt][0] + bx; o.y = c2[mt][nt][1] + by;
                    *(float2*)(g_h + (size_t)r0 * COUT + col) = o;
                    *(__nv_bfloat162*)(g_hb + (size_t)r0 * COUT + col) =
                        __floats2bfloat162_rn(o.x, o.y);
                }
                if (r0 + 8 < NV) {
                    float2 o; o.x = c2[mt][nt][2] + bx; o.y = c2[mt][nt][3] + by;
                    *(float2*)(g_h + (size_t)(r0 + 8) * COUT + col) = o;
                    *(__nv_bfloat162*)(g_hb + (size_t)(r0 + 8) * COUT + col) =
                        __floats2bfloat162_rn(o.x, o.y);
                }
            }
        }
    }
}

// ============ TMA bulk-reduce scatter =======================================
// Per warp batch of 8 pairs: 16 lanes/pair read bf16 row (8B/lane), convert,
// stage 256B f32 row in smem; lanes 0-7 each issue ONE
// cp.reduce.async.bulk (256B add.f32) + the count RED. Ping-pong ring,
// wait_group.read for buffer reuse.
__device__ __forceinline__ void tma_scatter_body(
    const __nv_bfloat16* __restrict__ feat,
    const int* __restrict__ sidx, const int* __restrict__ didx,
    float* __restrict__ sum, float* __restrict__ cnt,
    float (*my)[8][64])   // my[ping][slot][64]
{
    int lane = threadIdx.x & 31;
    int half = lane >> 4;      // pair within lane-group step
    int l = lane & 15;
    long long W  = (long long)blockIdx.x * 8 + ((threadIdx.x >> 5));
    long long TW = (long long)gridDim.x * 8;

    int it = 0;
    for (long long base = W * 8; base < NP; base += TW * 8, it++) {
        int ping = it & 1;
        if (lane < 8)
            asm volatile("cp.async.bulk.wait_group.read 1;" ::: "memory");
        __syncwarp();
#pragma unroll
        for (int u = 0; u < 4; u++) {
            long long p = base + u * 2 + half;
            int s = (p < NP) ? __ldg(sidx + p) : 0;
            uint2 raw = *(const uint2*)(feat + (size_t)s * COUT + l * 4);
            float2 lo = __bfloat1622float2(*(__nv_bfloat162*)&raw.x);
            float2 hi = __bfloat1622float2(*(__nv_bfloat162*)&raw.y);
            float4 v = make_float4(lo.x, lo.y, hi.x, hi.y);
            *(float4*)&my[ping][u * 2 + half][l * 4] = v;
        }
        asm volatile("fence.proxy.async.shared::cta;" ::: "memory");
        __syncwarp();
        if (lane < 8) {
            long long p = base + lane;
            if (p < NP) {
                int d = __ldg(didx + p);
                float* gp = sum + (size_t)d * COUT;
                uint32_t sa = (uint32_t)__cvta_generic_to_shared(&my[ping][lane][0]);
                asm volatile(
                    "cp.reduce.async.bulk.global.shared::cta.bulk_group.add.f32 "
                    "[%0], [%1], 256;"
                    :: "l"(gp), "r"(sa) : "memory");
                asm volatile("red.global.add.f32 [%0], %1;"
                             :: "l"(cnt + d), "f"(1.0f) : "memory");
            }
            asm volatile("cp.async.bulk.commit_group;" ::: "memory");
        }
    }
    if (lane < 8)
        asm volatile("cp.async.bulk.wait_group 0;" ::: "memory");
}

// 2D grid: y=0 -> v2e (h->esum), y=1 -> graph (h->gsum)
__global__ void __launch_bounds__(256, 4)
scatter2_tma(const int* __restrict__ hg_v, const int* __restrict__ hg_e,
             const int* __restrict__ g_srcp, const int* __restrict__ g_dstp) {
    __shared__ __align__(16) float sbuf[8][2][8][64];   // 32KB
    int wid = threadIdx.x >> 5;
    if (blockIdx.y == 0)
        tma_scatter_body(g_hb, hg_v, hg_e, g_esum, g_ecnt, sbuf[wid]);
    else
        tma_scatter_body(g_hb, g_srcp, g_dstp, g_gsum, g_vcnt_g, sbuf[wid]);
}

__global__ void __launch_bounds__(256, 4)
scatter_e2v_tma(const int* __restrict__ hg_e, const int* __restrict__ hg_v) {
    __shared__ __align__(16) float sbuf[8][2][8][64];
    int wid = threadIdx.x >> 5;
    tma_scatter_body(g_efb, hg_e, hg_v, g_hgsum, g_vcnt_hg, sbuf[wid]);
}

// ---------------- e_feat(bf16) = e_sum / max(cnt,1) -------------------------
__global__ void efeat_kernel() {
    int i = blockIdx.x * blockDim.x + threadIdx.x;
    if (i >= NE * COUT / 2) return;
    float c = fmaxf(g_ecnt[i >> 5], 1.0f);
    float inv = 1.0f / c;
    float2 v = ((const float2*)g_esum)[i];
    ((__nv_bfloat162*)g_efb)[i] = __floats2bfloat162_rn(v.x * inv, v.y * inv);
}

// ---------------- final fuse + activation ----------------------------------
__global__ void final_kernel(const float* __restrict__ w, float* __restrict__ out) {
    int t = blockIdx.x * blockDim.x + threadIdx.x;
    if (t >= NV * COUT / 4) return;
    int v = t >> 4;
    float e0 = expf(w[0]), e1 = expf(w[1]);
    float sw0 = e0 / (e0 + e1), sw1 = e1 / (e0 + e1);
    float ih = 1.0f / fmaxf(g_vcnt_hg[v], 1.0f);
    float ig = 1.0f / fmaxf(g_vcnt_g[v], 1.0f);
    float4 hg = ((const float4*)g_hgsum)[t];
    float4 gg = ((const float4*)g_gsum)[t];
    float4 h  = ((const float4*)g_h)[t];
    float4 o;
    o.x = lrelu(sw0 * 0.5f * (gg.x * ig + hg.x * ih) + sw1 * h.x);
    o.y = lrelu(sw0 * 0.5f * (gg.y * ig + hg.y * ih) + sw1 * h.y);
    o.z = lrelu(sw0 * 0.5f * (gg.z * ig + hg.z * ih) + sw1 * h.z);
    o.w = lrelu(sw0 * 0.5f * (gg.w * ig + hg.w * ih) + sw1 * h.w);
    ((float4*)out)[t] = o;
}

// ---------------- launch ----------------------------------------------------
extern "C" void kernel_launch(void* const* d_in, const int* in_sizes, int n_in,
                              void* d_out, int out_size) {
    const float* x    = (const float*)d_in[0];
    const float* W1   = (const float*)d_in[1];
    const float* b1   = (const float*)d_in[2];
    const float* W2   = (const float*)d_in[3];
    const float* b2   = (const float*)d_in[4];
    const float* w    = (const float*)d_in[5];
    const int*   hg_v = (const int*)d_in[6];
    const int*   hg_e = (const int*)d_in[7];
    const int*   g_src= (const int*)d_in[8];
    const int*   g_dst= (const int*)d_in[9];
    float* out = (float*)d_out;

    cudaFuncSetAttribute(gemm_fused, cudaFuncAttributeMaxDynamicSharedMemorySize,
                         GF_SMEM_BYTES);

    gemm_fused<<<148, 256, GF_SMEM_BYTES>>>(x, W1, b1, W2, b2);

    dim3 sgrid(1184, 2);
    scatter2_tma<<<sgrid, 256>>>(hg_v, hg_e, g_src, g_dst);
    efeat_kernel<<<(NE * COUT / 2 + 255) / 256, 256>>>();
    scatter_e2v_tma<<<1184, 256>>>(hg_e, hg_v);
    final_kernel<<<(NV * COUT / 4 + 255) / 256, 256>>>(w, out);
}